// round 12
// baseline (speedup 1.0000x reference)
#include <cuda_runtime.h>
#include <cuda_bf16.h>
#include <cstdint>
#include <math.h>

// ---------------------------------------------------------------------------
// Problem constants
// ---------------------------------------------------------------------------
#define NROW 64
#define NCLS 1000
#define FA 3
#define DA 65536
#define FB 4
#define DB 32768
#define BLKS_PER_A 29          // 3*29 = 87 blocks for group a
#define BLKS_PER_B 15          // 4*15 = 60 blocks for group b
#define GRID1 (FA * BLKS_PER_A + FB * BLKS_PER_B)   // 147
#define TILES_A (DA / 64)      // 1024
#define TILES_B (DB / 64)      // 512

// Scratch (no allocations allowed -> __device__ globals)
__device__ float  g_part[GRID1][4096];   // per-block partial Gram matrices
__device__ double g_ce_row[NROW];        // per-row CE contributions
__device__ double g_trkl_part[25][16];   // per-reduce2-block trkl partials
__device__ double g_rsum[7][64];         // row sums of each K

// ---------------------------------------------------------------------------
// helpers (ISA-portable: ldmatrix + mma.sync only; NO tcgen05)
// ---------------------------------------------------------------------------
__device__ __forceinline__ uint32_t smem_u32(const void* p) {
    uint32_t a;
    asm("{ .reg .u64 t; cvta.to.shared.u64 t, %1; cvt.u32.u64 %0, t; }"
        : "=r"(a) : "l"(p));
    return a;
}
__device__ __forceinline__ void ldmx4(uint32_t& r0, uint32_t& r1,
                                      uint32_t& r2, uint32_t& r3, uint32_t addr) {
    asm volatile("ldmatrix.sync.aligned.m8n8.x4.shared.b16 {%0,%1,%2,%3}, [%4];"
                 : "=r"(r0), "=r"(r1), "=r"(r2), "=r"(r3) : "r"(addr));
}
__device__ __forceinline__ void mma16816(float& c0, float& c1, float& c2, float& c3,
                                         uint32_t a0, uint32_t a1, uint32_t a2,
                                         uint32_t a3, uint32_t b0, uint32_t b1) {
    asm volatile(
        "mma.sync.aligned.m16n8k16.row.col.f32.bf16.bf16.f32 "
        "{%0,%1,%2,%3}, {%4,%5,%6,%7}, {%8,%9}, {%0,%1,%2,%3};"
        : "+f"(c0), "+f"(c1), "+f"(c2), "+f"(c3)
        : "r"(a0), "r"(a1), "r"(a2), "r"(a3), "r"(b0), "r"(b1));
}
__device__ __forceinline__ uint32_t swz(uint32_t off) {   // SW128 swizzle
    return off ^ ((off >> 3) & 0x70);
}

// ---------------------------------------------------------------------------
// Phase 1: Gram K = X X^T via bf16-split warp MMA (HMMA).
// x = hi + lo (two bf16); K ~= Hi Hi^T + Hi Lo^T + Lo Hi^T  (lo*lo dropped,
// relative contribution ~2^-18 << 1e-3 gate).
// Per 64-col chunk: convert to two 64x64 bf16 SW128 tiles; 8 warps each own
// an m16 x n32 block with fp32 register accumulators across all chunks.
// ---------------------------------------------------------------------------
__global__ __launch_bounds__(256, 1)
void gram_hmma(const float* __restrict__ A, const float* __restrict__ B) {
    int b = blockIdx.x;
    const float* X;
    long long D;
    int t0, t1;
    if (b < FA * BLKS_PER_A) {
        int f = b / BLKS_PER_A, lb = b % BLKS_PER_A;
        X = A + (long long)f * NROW * DA;
        D = DA;
        t0 = lb * TILES_A / BLKS_PER_A;
        t1 = (lb + 1) * TILES_A / BLKS_PER_A;
    } else {
        int bb = b - FA * BLKS_PER_A;
        int f = bb / BLKS_PER_B, lb = bb % BLKS_PER_B;
        X = B + (long long)f * NROW * DB;
        D = DB;
        t0 = lb * TILES_B / BLKS_PER_B;
        t1 = (lb + 1) * TILES_B / BLKS_PER_B;
    }

    __shared__ __align__(1024) unsigned char sHi[8192];   // 64 x 64 bf16
    __shared__ __align__(1024) unsigned char sLo[8192];

    int tid = threadIdx.x, wid = tid >> 5, lane = tid & 31;
    uint32_t hiB = smem_u32(sHi), loB = smem_u32(sLo);

    // warp tile: rows m0..m0+15, cols n0..n0+31 of the 64x64 output
    int m0 = (wid & 3) * 16;
    int n0 = (wid >> 2) * 32;

    float acc[4][4];                 // 4 n8-tiles x 4 f32 regs
#pragma unroll
    for (int t = 0; t < 4; t++)
#pragma unroll
        for (int q = 0; q < 4; q++) acc[t][q] = 0.f;

    // conversion-store geometry: thread handles rows r0,r0+16,r0+32,r0+48
    int c4 = tid & 15;               // float4 index in row (16 per 64-col row)
    int r0 = tid >> 4;

    // ldmatrix address geometry (per kstep s, byte base 32*s):
    //   A frag : row = m0 + (lane&15), byte = (lane>>4)*16
    //   B frags: rows n0+(lane&15) and n0+16+(lane&15), same byte offset
    int lrow = lane & 15, lcol = (lane >> 4) * 16;
    uint32_t offA  = (uint32_t)(m0 + lrow) * 128 + lcol;
    uint32_t offB0 = (uint32_t)(n0 + lrow) * 128 + lcol;
    uint32_t offB1 = (uint32_t)(n0 + 16 + lrow) * 128 + lcol;

    // prefetch chunk t0
    float4 pf[4];
    {
        const float* p0 = X + (long long)t0 * 64 + 4 * c4;
#pragma unroll
        for (int i = 0; i < 4; i++)
            pf[i] = *(const float4*)(p0 + (long long)(r0 + 16 * i) * D);
    }

    for (int tt = t0; tt < t1; tt++) {
        // convert fp32 -> hi/lo bf16, swizzled stores
#pragma unroll
        for (int i = 0; i < 4; i++) {
            int row = r0 + 16 * i;
            float4 v = pf[i];
            uint32_t h01, h23, l01, l23;
            asm("cvt.rn.bf16x2.f32 %0, %1, %2;" : "=r"(h01) : "f"(v.y), "f"(v.x));
            asm("cvt.rn.bf16x2.f32 %0, %1, %2;" : "=r"(h23) : "f"(v.w), "f"(v.z));
            float fx = __uint_as_float(h01 << 16);
            float fy = __uint_as_float(h01 & 0xFFFF0000u);
            float fz = __uint_as_float(h23 << 16);
            float fw = __uint_as_float(h23 & 0xFFFF0000u);
            asm("cvt.rn.bf16x2.f32 %0, %1, %2;" : "=r"(l01) : "f"(v.y - fy), "f"(v.x - fx));
            asm("cvt.rn.bf16x2.f32 %0, %1, %2;" : "=r"(l23) : "f"(v.w - fw), "f"(v.z - fz));
            uint32_t sw = swz((uint32_t)row * 128 + c4 * 8);
            *(uint2*)(sHi + sw) = make_uint2(h01, h23);
            *(uint2*)(sLo + sw) = make_uint2(l01, l23);
        }
        // prefetch next chunk (global latency overlaps the MMA section)
        if (tt + 1 < t1) {
            const float* pn = X + (long long)(tt + 1) * 64 + 4 * c4;
#pragma unroll
            for (int i = 0; i < 4; i++)
                pf[i] = *(const float4*)(pn + (long long)(r0 + 16 * i) * D);
        }
        __syncthreads();

#pragma unroll
        for (int s = 0; s < 4; s++) {               // 4 K16 steps per chunk
            uint32_t kb = 32u * s;
            uint32_t ah0, ah1, ah2, ah3, al0, al1, al2, al3;
            ldmx4(ah0, ah1, ah2, ah3, hiB + swz(offA + kb));
            ldmx4(al0, al1, al2, al3, loB + swz(offA + kb));
            // B: regs rX0=(n0-7 frag b0), rX1=(n8-15 b0), rX2=(n0-7 b1), rX3=(n8-15 b1)
            uint32_t bh[4][2], bl[4][2];
            {
                uint32_t q0, q1, q2, q3;
                ldmx4(q0, q1, q2, q3, hiB + swz(offB0 + kb));
                bh[0][0] = q0; bh[1][0] = q1; bh[0][1] = q2; bh[1][1] = q3;
                ldmx4(q0, q1, q2, q3, hiB + swz(offB1 + kb));
                bh[2][0] = q0; bh[3][0] = q1; bh[2][1] = q2; bh[3][1] = q3;
                ldmx4(q0, q1, q2, q3, loB + swz(offB0 + kb));
                bl[0][0] = q0; bl[1][0] = q1; bl[0][1] = q2; bl[1][1] = q3;
                ldmx4(q0, q1, q2, q3, loB + swz(offB1 + kb));
                bl[2][0] = q0; bl[3][0] = q1; bl[2][1] = q2; bl[3][1] = q3;
            }
#pragma unroll
            for (int t = 0; t < 4; t++) {
                mma16816(acc[t][0], acc[t][1], acc[t][2], acc[t][3],
                         ah0, ah1, ah2, ah3, bh[t][0], bh[t][1]);
                mma16816(acc[t][0], acc[t][1], acc[t][2], acc[t][3],
                         ah0, ah1, ah2, ah3, bl[t][0], bl[t][1]);
                mma16816(acc[t][0], acc[t][1], acc[t][2], acc[t][3],
                         al0, al1, al2, al3, bh[t][0], bh[t][1]);
            }
        }
        __syncthreads();
    }

    // epilogue: m16n8 accumulator layout -> g_part[b]
    // thread: rows m0 + lane/4 (+8), cols ntile*8 + (lane%4)*2 (+1)
    float* P = g_part[b];
    int arow = m0 + (lane >> 2);
    int acol = n0 + (lane & 3) * 2;
#pragma unroll
    for (int t = 0; t < 4; t++) {
        *(float2*)(P + arow * 64 + acol + 8 * t) =
            make_float2(acc[t][0], acc[t][1]);
        *(float2*)(P + (arow + 8) * 64 + acol + 8 * t) =
            make_float2(acc[t][2], acc[t][3]);
    }
}

// ---------------------------------------------------------------------------
// Phase 2 (fused): partials -> K element (regs, diag zeroed) -> rowsums +
// 25 trkl block-partials. grid 16 x 256, no atomics (deterministic).
// ---------------------------------------------------------------------------
__global__ __launch_bounds__(256, 1) void reduce2() {
    int tid = threadIdx.x;
    int e = blockIdx.x * 256 + tid;   // 0..4095
    int n = e >> 6, m = e & 63;
    int wid = tid >> 5, lane = tid & 31;

    double Kv[7];
    if (n != m) {
#pragma unroll
        for (int f = 0; f < 7; f++) {
            int b0 = (f < FA) ? f * BLKS_PER_A
                              : FA * BLKS_PER_A + (f - FA) * BLKS_PER_B;
            int nb = (f < FA) ? BLKS_PER_A : BLKS_PER_B;
            double s = 0.0;
#pragma unroll
            for (int k = 0; k < nb; k++) s += (double)g_part[b0 + k][e];
            Kv[f] = s;
        }
    } else {
#pragma unroll
        for (int f = 0; f < 7; f++) Kv[f] = 0.0;
    }

    __shared__ double wred[8];
    // rowsums: block covers rows [4*blk, 4*blk+4); row n spans warps (2l, 2l+1)
#pragma unroll
    for (int f = 0; f < 7; f++) {
        double v = Kv[f];
#pragma unroll
        for (int o = 16; o > 0; o >>= 1) v += __shfl_down_sync(0xffffffffu, v, o);
        if (lane == 0) wred[wid] = v;
        __syncthreads();
        if (tid < 4)
            g_rsum[f][blockIdx.x * 4 + tid] = wred[2 * tid] + wred[2 * tid + 1];
        __syncthreads();
    }
    // trkl partials
#pragma unroll
    for (int p = 0; p < 25; p++) {
        int fi, fj;
        if (p < 9) { fi = p / 3; fj = p % 3; }
        else       { int q = p - 9; fi = 3 + q / 4; fj = 3 + q % 4; }
        double v = Kv[fi] * Kv[fj];
#pragma unroll
        for (int o = 16; o > 0; o >>= 1) v += __shfl_down_sync(0xffffffffu, v, o);
        if (lane == 0) wred[wid] = v;
        __syncthreads();
        if (tid == 0)
            g_trkl_part[p][blockIdx.x] = wred[0] + wred[1] + wred[2] + wred[3] +
                                         wred[4] + wred[5] + wred[6] + wred[7];
        __syncthreads();
    }
}

// ---------------------------------------------------------------------------
// CE: one block per row; on-device target dtype sniff (int32 vs int64).
// ---------------------------------------------------------------------------
__global__ void ce_kernel(const float* __restrict__ logits,
                          const void* __restrict__ tgt_raw) {
    int row = blockIdx.x;
    const float* x = logits + row * NCLS;
    __shared__ float  redf[256];
    __shared__ double redd[256];
    int tid = threadIdx.x;

    float m = -1e30f;
    for (int c = tid; c < NCLS; c += 256) m = fmaxf(m, x[c]);
    redf[tid] = m;
    __syncthreads();
    for (int s = 128; s > 0; s >>= 1) {
        if (tid < s) redf[tid] = fmaxf(redf[tid], redf[tid + s]);
        __syncthreads();
    }
    float M = redf[0];
    __syncthreads();

    double se = 0.0;
    for (int c = tid; c < NCLS; c += 256) se += exp((double)(x[c] - M));
    redd[tid] = se;
    __syncthreads();
    for (int s = 128; s > 0; s >>= 1) {
        if (tid < s) redd[tid] += redd[tid + s];
        __syncthreads();
    }
    if (tid == 0) {
        const int* ti = (const int*)tgt_raw;
        bool odd_zero = true;
        for (int k = 1; k < 64; k += 2) odd_zero &= (ti[k] == 0);
        long long t;
        if (odd_zero) t = ((const long long*)tgt_raw)[row];
        else          t = (long long)ti[row];
        if (t < 0 || t >= NCLS) t = 0;
        g_ce_row[row] = -((double)x[t] - (double)M - log(redd[0]));
    }
}

// ---------------------------------------------------------------------------
// Finalize: cooperative staging into shared, parallel partial reductions,
// small scalar combine on thread 0.
// ---------------------------------------------------------------------------
__global__ __launch_bounds__(256, 1) void finalize(float* __restrict__ out) {
    __shared__ double r_sh[7 * 64];
    __shared__ double tr_sh[25];
    __shared__ double s_sh[7];
    __shared__ double rr_sh[25];
    __shared__ double ce_red[64];
    int tid = threadIdx.x;

    for (int idx = tid; idx < 7 * 64; idx += 256)
        r_sh[idx] = ((const double*)g_rsum)[idx];
    if (tid < 64) ce_red[tid] = g_ce_row[tid];
    if (tid >= 64 && tid < 89) {
        int p = tid - 64;
        double s = 0.0;
#pragma unroll
        for (int k = 0; k < 16; k++) s += g_trkl_part[p][k];
        tr_sh[p] = s;
    }
    __syncthreads();

    if (tid < 7) {
        double a = 0.0;
#pragma unroll 8
        for (int n = 0; n < 64; n++) a += r_sh[tid * 64 + n];
        s_sh[tid] = a;
    }
    if (tid >= 32 && tid < 57) {
        int p = tid - 32;
        int fi, fj;
        if (p < 9) { fi = p / 3; fj = p % 3; }
        else       { int q = p - 9; fi = 3 + q / 4; fj = 3 + q % 4; }
        double rr = 0.0;
#pragma unroll 8
        for (int n = 0; n < 64; n++)
            rr += r_sh[fi * 64 + n] * r_sh[fj * 64 + n];
        rr_sh[p] = rr;
    }
    __syncthreads();
    for (int s = 32; s > 0; s >>= 1) {
        if (tid < s) ce_red[tid] += ce_red[tid + s];
        __syncthreads();
    }

    if (tid == 0) {
        const double c1 = 63.0 * 62.0;   // (N-1)(N-2)
        const double c2 = 62.0;          // (N-2)
        const double c3 = 64.0 * 61.0;   // N(N-3)
        double cka = 0.0;
        for (int g = 0; g < 2; g++) {
            int F = g ? 4 : 3;
            int base = g ? 3 : 0;
            int pbase = g ? 9 : 0;
            double hs[4][4], dd[4];
            for (int i = 0; i < F; i++)
                for (int j = 0; j < F; j++) {
                    int p = pbase + i * F + j;
                    hs[i][j] = (tr_sh[p] +
                                s_sh[base + i] * s_sh[base + j] / c1 -
                                2.0 * rr_sh[p] / c2) / c3;
                }
            for (int i = 0; i < F; i++) dd[i] = sqrt(hs[i][i]);
            for (int i = 0; i < F; i++)
                for (int j = 0; j < F; j++)
                    cka += hs[i][j] / (dd[i] * dd[j]);
        }
        double ce = ce_red[0] / (double)NROW;
        out[0] = (float)(ce + 0.1 * cka);
    }
}

// ---------------------------------------------------------------------------
extern "C" void kernel_launch(void* const* d_in, const int* in_sizes, int n_in,
                              void* d_out, int out_size) {
    const float* logits = nullptr;
    const void*  tgt    = nullptr;
    const float* fa     = nullptr;
    const float* fb     = nullptr;
    for (int i = 0; i < n_in; i++) {
        int s = in_sizes[i];
        if (s == NROW * NCLS)           logits = (const float*)d_in[i];
        else if (s == NROW)             tgt    = d_in[i];
        else if (s == FA * NROW * DA)   fa     = (const float*)d_in[i];
        else if (s == FB * NROW * DB)   fb     = (const float*)d_in[i];
    }
    float* out = (float*)d_out;

    ce_kernel<<<NROW, 256>>>(logits, tgt);
    gram_hmma<<<GRID1, 256>>>(fa, fb);
    reduce2<<<16, 256>>>();
    finalize<<<1, 256>>>(out);
    cudaMemcpyAsync(out + 1, logits, NROW * NCLS * sizeof(float),
                    cudaMemcpyDeviceToDevice, 0);
}